// round 2
// baseline (speedup 1.0000x reference)
#include <cuda_runtime.h>
#include <math.h>

#define BB   128
#define TT   256
#define EE   384
#define HH   6
#define DHH  64
#define LL   6
#define VV   65
#define FFD  1536
#define BT   (BB*TT)          // 32768
#define E3   (3*EE)           // 1152
#define EPSV 1e-5f

// ---------------- scratch (device globals; no allocation allowed) ----------------
__device__ float g_x[BT*EE];        // residual stream
__device__ float g_h[BT*EE];        // LN output
__device__ float g_qkv[BT*E3];      // fused qkv
__device__ float g_att[BT*EE];      // attention output (concat heads)
__device__ float g_ff[BT*FFD];      // FF hidden
__device__ float g_wqkv[EE*E3];     // per-layer transposed qkv weights [E, 3E]
__device__ float g_nll[BT];         // per-token nll

// ---------------- embedding ----------------
__global__ void embed_kernel(const int* __restrict__ idx,
                             const float* __restrict__ tok,
                             const float* __restrict__ pos) {
    int i = blockIdx.x * blockDim.x + threadIdx.x;
    if (i >= BT * EE) return;
    int e  = i % EE;
    int bt = i / EE;
    int t  = bt % TT;
    g_x[i] = tok[idx[bt] * EE + e] + pos[t * EE + e];
}

// ---------------- layernorm: g_x -> g_h ----------------
__global__ void ln_kernel(const float* __restrict__ s, const float* __restrict__ b) {
    int tok = blockIdx.x;
    int tid = threadIdx.x;                 // 128 threads
    const float* row = g_x + (size_t)tok * EE;
    float v0 = row[tid], v1 = row[tid + 128], v2 = row[tid + 256];

    float sum = v0 + v1 + v2;
    __shared__ float red[4], red2[4];
    #pragma unroll
    for (int o = 16; o; o >>= 1) sum += __shfl_xor_sync(~0u, sum, o);
    if ((tid & 31) == 0) red[tid >> 5] = sum;
    __syncthreads();
    float mean = (red[0] + red[1] + red[2] + red[3]) * (1.f / EE);

    float d0 = v0 - mean, d1 = v1 - mean, d2 = v2 - mean;
    float vs = d0 * d0 + d1 * d1 + d2 * d2;
    #pragma unroll
    for (int o = 16; o; o >>= 1) vs += __shfl_xor_sync(~0u, vs, o);
    if ((tid & 31) == 0) red2[tid >> 5] = vs;
    __syncthreads();
    float var = (red2[0] + red2[1] + red2[2] + red2[3]) * (1.f / EE);
    float inv = rsqrtf(var + EPSV);

    float* out = g_h + (size_t)tok * EE;
    out[tid]       = d0 * inv * s[tid]       + b[tid];
    out[tid + 128] = d1 * inv * s[tid + 128] + b[tid + 128];
    out[tid + 256] = d2 * inv * s[tid + 256] + b[tid + 256];
}

// ---------------- qkv weight transpose for layer l: [H,E,DH]x3 -> [E, 3E] ----------------
__global__ void tq_kernel(const float* __restrict__ Wq, const float* __restrict__ Wk,
                          const float* __restrict__ Wv, int l) {
    int i = blockIdx.x * blockDim.x + threadIdx.x;
    if (i >= HH * EE * DHH) return;
    int d = i % DHH;
    int e = (i / DHH) % EE;
    int h = i / (DHH * EE);
    int src = ((l * HH + h) * EE + e) * DHH + d;
    int col = h * DHH + d;
    g_wqkv[e * E3 + col]          = Wq[src];
    g_wqkv[e * E3 + EE + col]     = Wk[src];
    g_wqkv[e * E3 + 2 * EE + col] = Wv[src];
}

// ---------------- 128x128x8 SGEMM, fused epilogue ----------------
// MODE bits: 1 = +bias[n], 2 = +resid[m*N+n], 4 = relu
template <int MODE>
__global__ void gemm128(const float* __restrict__ A, const float* __restrict__ B,
                        const float* __restrict__ bias, const float* __restrict__ resid,
                        float* __restrict__ C, int M, int N, int K) {
    __shared__ float As[8][128];
    __shared__ float Bs[8][128];
    int m0 = blockIdx.x * 128;    // M tile (fast dim -> consecutive blocks share B tile)
    int n0 = blockIdx.y * 128;
    int tid = threadIdx.x;        // 256
    int row_c = (tid >> 4) << 3;  // 0..120
    int col_c = (tid & 15) << 3;  // 0..120

    float acc[8][8];
    #pragma unroll
    for (int i = 0; i < 8; i++)
        #pragma unroll
        for (int j = 0; j < 8; j++) acc[i][j] = 0.f;

    int ar = tid >> 1;            // 0..127
    int ac = (tid & 1) << 2;      // 0 / 4
    int br = tid >> 5;            // 0..7
    int bc = (tid & 31) << 2;     // 0..124

    for (int k0 = 0; k0 < K; k0 += 8) {
        float4 av = *(const float4*)(A + (size_t)(m0 + ar) * K + k0 + ac);
        float4 bv = *(const float4*)(B + (size_t)(k0 + br) * N + n0 + bc);
        As[ac + 0][ar] = av.x; As[ac + 1][ar] = av.y;
        As[ac + 2][ar] = av.z; As[ac + 3][ar] = av.w;
        *(float4*)&Bs[br][bc] = bv;
        __syncthreads();
        #pragma unroll
        for (int k = 0; k < 8; k++) {
            float a[8], bb[8];
            #pragma unroll
            for (int i = 0; i < 8; i++) a[i] = As[k][row_c + i];
            #pragma unroll
            for (int j = 0; j < 8; j++) bb[j] = Bs[k][col_c + j];
            #pragma unroll
            for (int i = 0; i < 8; i++)
                #pragma unroll
                for (int j = 0; j < 8; j++)
                    acc[i][j] = fmaf(a[i], bb[j], acc[i][j]);
        }
        __syncthreads();
    }

    #pragma unroll
    for (int i = 0; i < 8; i++) {
        int m = m0 + row_c + i;
        #pragma unroll
        for (int j = 0; j < 8; j++) {
            int n = n0 + col_c + j;
            float v = acc[i][j];
            if (MODE & 1) v += bias[n];
            if (MODE & 2) v += resid[(size_t)m * N + n];
            if (MODE & 4) v = fmaxf(v, 0.f);
            C[(size_t)m * N + n] = v;
        }
    }
}

// ---------------- attention: one block per (b,h), flash-style online softmax ----------------
__global__ void attn_kernel() {
    extern __shared__ float sm[];
    float* Ks = sm;                 // [256][64]
    float* Vs = sm + TT * DHH;      // [256][64]
    int b = blockIdx.x / HH;
    int h = blockIdx.x % HH;
    int tid = threadIdx.x;          // 256

    const float* base = g_qkv + (size_t)b * TT * E3;
    for (int i = tid; i < TT * DHH / 4; i += blockDim.x) {
        int srow = i >> 4;          // 16 float4 per row
        int c4 = (i & 15) << 2;
        *(float4*)&Ks[srow * DHH + c4] = *(const float4*)(base + (size_t)srow * E3 + EE + h * DHH + c4);
        *(float4*)&Vs[srow * DHH + c4] = *(const float4*)(base + (size_t)srow * E3 + 2 * EE + h * DHH + c4);
    }
    __syncthreads();

    int t = tid;
    float q[DHH];
    const float* qp = base + (size_t)t * E3 + h * DHH;
    #pragma unroll
    for (int d = 0; d < DHH; d++) q[d] = qp[d] * 0.125f;   // scale = DH^-0.5

    float acc[DHH];
    #pragma unroll
    for (int d = 0; d < DHH; d++) acc[d] = 0.f;
    float m = -1e30f, l = 0.f;

    for (int s = 0; s < TT; s++) {
        if (s > t) break;
        float sc = 0.f;
        #pragma unroll
        for (int d = 0; d < DHH; d++) sc = fmaf(q[d], Ks[s * DHH + d], sc);
        float nm = fmaxf(m, sc);
        float corr = __expf(m - nm);
        float p = __expf(sc - nm);
        l = l * corr + p;
        #pragma unroll
        for (int d = 0; d < DHH; d++)
            acc[d] = fmaf(acc[d], corr, p * Vs[s * DHH + d]);
        m = nm;
    }

    float inv = 1.f / l;
    float* op = g_att + ((size_t)(b * TT + t)) * EE + h * DHH;
    #pragma unroll
    for (int d = 0; d < DHH; d++) op[d] = acc[d] * inv;
}

// ---------------- fused logits + log_softmax + nll (reads g_h) ----------------
__global__ void logits_kernel(const float* __restrict__ Wout, const float* __restrict__ bout,
                              const int* __restrict__ tgt, float* __restrict__ out) {
    __shared__ float hs[EE];
    __shared__ float sl[128];
    __shared__ float slog[VV];
    int tok = blockIdx.x;
    int tid = threadIdx.x;          // 128
    const float* row = g_h + (size_t)tok * EE;
    hs[tid] = row[tid]; hs[tid + 128] = row[tid + 128]; hs[tid + 256] = row[tid + 256];
    __syncthreads();

    float logit = -1e30f;
    if (tid < VV) {
        float s = bout[tid];
        #pragma unroll 4
        for (int e = 0; e < EE; e++) s = fmaf(hs[e], Wout[e * VV + tid], s);
        logit = s;
        slog[tid] = s;
        out[(size_t)tok * VV + tid] = s;
    }
    sl[tid] = logit;
    __syncthreads();
    for (int o = 64; o; o >>= 1) { if (tid < o) sl[tid] = fmaxf(sl[tid], sl[tid + o]); __syncthreads(); }
    float mx = sl[0];
    __syncthreads();
    sl[tid] = (tid < VV) ? __expf(logit - mx) : 0.f;
    __syncthreads();
    for (int o = 64; o; o >>= 1) { if (tid < o) sl[tid] += sl[tid + o]; __syncthreads(); }
    if (tid == 0) {
        float logZ = mx + __logf(sl[0]);
        g_nll[tok] = logZ - slog[tgt[tok]];
    }
}

// ---------------- deterministic loss reduction ----------------
__global__ void loss_kernel(float* __restrict__ out) {
    __shared__ float red[256];
    float s = 0.f;
    for (int i = threadIdx.x; i < BT; i += 256) s += g_nll[i];
    red[threadIdx.x] = s;
    __syncthreads();
    for (int o = 128; o; o >>= 1) { if (threadIdx.x < o) red[threadIdx.x] += red[threadIdx.x + o]; __syncthreads(); }
    if (threadIdx.x == 0) out[(size_t)BT * VV] = red[0] * (1.f / BT);
}

// ---------------- host orchestration ----------------
extern "C" void kernel_launch(void* const* d_in, const int* in_sizes, int n_in,
                              void* d_out, int out_size) {
    const int*   idx  = (const int*)d_in[0];
    const int*   tgt  = (const int*)d_in[1];
    const float* tok  = (const float*)d_in[2];
    const float* pos  = (const float*)d_in[3];
    const float* Wq   = (const float*)d_in[4];
    const float* Wk   = (const float*)d_in[5];
    const float* Wv   = (const float*)d_in[6];
    const float* Wo   = (const float*)d_in[7];
    const float* bo   = (const float*)d_in[8];
    const float* l1s  = (const float*)d_in[9];
    const float* l1b  = (const float*)d_in[10];
    const float* l2s  = (const float*)d_in[11];
    const float* l2b  = (const float*)d_in[12];
    const float* W1   = (const float*)d_in[13];
    const float* b1   = (const float*)d_in[14];
    const float* W2   = (const float*)d_in[15];
    const float* b2   = (const float*)d_in[16];
    const float* lnfs = (const float*)d_in[17];
    const float* lnfb = (const float*)d_in[18];
    const float* Wout = (const float*)d_in[19];
    const float* bout = (const float*)d_in[20];
    float* out = (float*)d_out;

    cudaFuncSetAttribute(attn_kernel, cudaFuncAttributeMaxDynamicSharedMemorySize,
                         2 * TT * DHH * (int)sizeof(float));

    float *px, *ph, *pqkv, *patt, *pff, *pwqkv;
    cudaGetSymbolAddress((void**)&px,    g_x);
    cudaGetSymbolAddress((void**)&ph,    g_h);
    cudaGetSymbolAddress((void**)&pqkv,  g_qkv);
    cudaGetSymbolAddress((void**)&patt,  g_att);
    cudaGetSymbolAddress((void**)&pff,   g_ff);
    cudaGetSymbolAddress((void**)&pwqkv, g_wqkv);

    embed_kernel<<<(BT * EE + 255) / 256, 256>>>(idx, tok, pos);

    for (int l = 0; l < LL; l++) {
        ln_kernel<<<BT, 128>>>(l1s + l * EE, l1b + l * EE);
        tq_kernel<<<(HH * EE * DHH + 255) / 256, 256>>>(Wq, Wk, Wv, l);
        // qkv = h @ Wqkv_t  [BT,384]@[384,1152]
        gemm128<0><<<dim3(BT / 128, E3 / 128), 256>>>(ph, pwqkv, nullptr, nullptr, pqkv, BT, E3, EE);
        attn_kernel<<<BB * HH, TT, 2 * TT * DHH * sizeof(float)>>>();
        // x = x + att @ Wo + bo
        gemm128<1 | 2><<<dim3(BT / 128, EE / 128), 256>>>(patt, Wo + (size_t)l * EE * EE, bo + l * EE, px, px, BT, EE, EE);
        ln_kernel<<<BT, 128>>>(l2s + l * EE, l2b + l * EE);
        // ff = relu(h @ W1 + b1)
        gemm128<1 | 4><<<dim3(BT / 128, FFD / 128), 256>>>(ph, W1 + (size_t)l * EE * FFD, b1 + l * FFD, nullptr, pff, BT, FFD, EE);
        // x = x + ff @ W2 + b2
        gemm128<1 | 2><<<dim3(BT / 128, EE / 128), 256>>>(pff, W2 + (size_t)l * FFD * EE, b2 + l * EE, px, px, BT, EE, FFD);
    }

    ln_kernel<<<BT, 128>>>(lnfs, lnfb);
    logits_kernel<<<BT, 128>>>(Wout, bout, tgt, out);
    loss_kernel<<<1, 256>>>(out);
}